// round 5
// baseline (speedup 1.0000x reference)
#include <cuda_runtime.h>

// x_ref, x : [B=4, C=3, H=512, W=512] float32
// out: [4,3,512,512] f32 (3145728) then best_shifts [4,2] as floats (8)

#define NIMG   12
#define HH     512
#define WW     512
#define W4     (WW/4)       // 128 float4 per row
#define NSHIFT 81
#define IMG_ELEMS (HH*WW)
#define OUT_IMG   (NIMG*IMG_ELEMS)   // 3145728
#define NBLK   384          // corr grid: 12 imgs * 32 blocks

__device__ float g_partial[NBLK * NSHIFT];   // per-block partial sims
__device__ int2  g_best[4];

// ---------------------------------------------------------------------------
// Phase 1: 81-shift correlation, reading x_ref directly (no padded copy).
// Thread: 4 rows x 8 cols of one image, dx-outer, 9 live accumulators.
// Block = 256 thr = 4 rowgroups x 64 strips; 32 blocks per image.
// Per-block result -> g_partial[block][81] (deterministic, no global atomics).
// ---------------------------------------------------------------------------
__global__ void __launch_bounds__(256) corr_kernel(const float* __restrict__ x,
                                                   const float* __restrict__ xref) {
    __shared__ float ssum[NSHIFT];
    if (threadIdx.x < NSHIFT) ssum[threadIdx.x] = 0.0f;
    __syncthreads();

    int img   = blockIdx.x >> 5;
    int strip = threadIdx.x & 63;
    int rgrp  = ((blockIdx.x & 31) << 2) + (threadIdx.x >> 6);
    int a0    = rgrp * 4;
    int j0    = strip * 8;
    int lane  = threadIdx.x & 31;

    // preload x strip: 4 rows x 8 cols (32 regs)
    const float4* xp4 = (const float4*)x + (size_t)img * HH * W4;
    float xv[32];
#pragma unroll
    for (int r = 0; r < 4; r++) {
        float4 m0 = __ldg(xp4 + (a0 + r) * W4 + (j0 >> 2));
        float4 m1 = __ldg(xp4 + (a0 + r) * W4 + (j0 >> 2) + 1);
        xv[r * 8 + 0] = m0.x; xv[r * 8 + 1] = m0.y;
        xv[r * 8 + 2] = m0.z; xv[r * 8 + 3] = m0.w;
        xv[r * 8 + 4] = m1.x; xv[r * 8 + 5] = m1.y;
        xv[r * 8 + 6] = m1.z; xv[r * 8 + 7] = m1.w;
    }

    const float4* ref4 = (const float4*)xref + (size_t)img * HH * W4;
    const bool leftok  = (j0 != 0);
    const bool rightok = (j0 != WW - 8);
    const int  jb      = (j0 >> 2) - 1;   // float4 col of j0-4 (16B aligned)
    const float4 z4 = make_float4(0.f, 0.f, 0.f, 0.f);

#pragma unroll 1
    for (int dx = 0; dx < 9; dx++) {
        float acc[9];
#pragma unroll
        for (int d = 0; d < 9; d++) acc[d] = 0.0f;

#pragma unroll
        for (int r = 0; r < 4; r++) {
            int ar = a0 + r + dx - 4;
            bool rowok = (unsigned)ar < (unsigned)HH;
            const float4* rp = ref4 + ar * W4 + jb;
            float4 q0 = (rowok && leftok)  ? __ldg(rp + 0) : z4;
            float4 q1 = rowok              ? __ldg(rp + 1) : z4;
            float4 q2 = rowok              ? __ldg(rp + 2) : z4;
            float4 q3 = (rowok && rightok) ? __ldg(rp + 3) : z4;
            float rv[16] = {q0.x, q0.y, q0.z, q0.w, q1.x, q1.y, q1.z, q1.w,
                            q2.x, q2.y, q2.z, q2.w, q3.x, q3.y, q3.z, q3.w};
#pragma unroll
            for (int p = 0; p < 8; p++) {
#pragma unroll
                for (int d = 0; d < 9; d++) {
                    acc[d] += xv[r * 8 + p] * rv[p + d];
                }
            }
        }

        // warp butterfly per dy, then one-lane atomic into block smem
#pragma unroll
        for (int d = 0; d < 9; d++) {
            float v = acc[d];
            v += __shfl_xor_sync(0xffffffffu, v, 16);
            v += __shfl_xor_sync(0xffffffffu, v, 8);
            v += __shfl_xor_sync(0xffffffffu, v, 4);
            v += __shfl_xor_sync(0xffffffffu, v, 2);
            v += __shfl_xor_sync(0xffffffffu, v, 1);
            int s = dx * 9 + d;
            if (lane == (s & 31)) atomicAdd(&ssum[s], v);
        }
    }

    __syncthreads();
    if (threadIdx.x < NSHIFT)
        g_partial[blockIdx.x * NSHIFT + threadIdx.x] = ssum[threadIdx.x];
}

// ---------------------------------------------------------------------------
// Phase 2: deterministic reduce of 96 partials per (batch,shift), then
// per-batch argmax (first-max tie-break, matching jnp.argmax).
// ---------------------------------------------------------------------------
__global__ void __launch_bounds__(384) reduce_argmax_kernel(float* __restrict__ d_out,
                                                            int out_size) {
    __shared__ float sims[4 * NSHIFT];
    int t = threadIdx.x;
    if (t < 4 * NSHIFT) {
        int b = t / NSHIFT;
        int s = t - b * NSHIFT;
        const float* pp = g_partial + (size_t)b * 96 * NSHIFT + s;
        float acc = 0.0f;
#pragma unroll 8
        for (int i = 0; i < 96; i++) acc += pp[i * NSHIFT];
        sims[t] = acc;
    }
    __syncthreads();

    int w = t >> 5, lane = t & 31;
    if (w < 4) {
        float bv = -3.0e38f;
        int bi = NSHIFT;
        for (int s = lane; s < NSHIFT; s += 32) {
            float v = sims[w * NSHIFT + s];
            if (v > bv || (v == bv && s < bi)) { bv = v; bi = s; }
        }
#pragma unroll
        for (int off = 16; off; off >>= 1) {
            float ov = __shfl_xor_sync(0xffffffffu, bv, off);
            int   oi = __shfl_xor_sync(0xffffffffu, bi, off);
            if (ov > bv || (ov == bv && oi < bi)) { bv = ov; bi = oi; }
        }
        if (lane == 0) {
            int sx = bi / 9 - 4;
            int sy = bi % 9 - 4;
            g_best[w] = make_int2(sx, sy);
            if (out_size >= OUT_IMG + 8) {
                d_out[OUT_IMG + w * 2 + 0] = (float)sx;
                d_out[OUT_IMG + w * 2 + 1] = (float)sy;
            }
        }
    }
}

// ---------------------------------------------------------------------------
// Phase 3: apply best shift. 2 aligned LDG.128 + warp-uniform extract + STG.128.
// Aligned 4-col blocks are entirely in or out of [0,512), so block-granular
// zeroing gives exact element masking.
// ---------------------------------------------------------------------------
__global__ void __launch_bounds__(256) apply_kernel(const float* __restrict__ x,
                                                    float* __restrict__ out) {
    int t = blockIdx.x * 256 + threadIdx.x;      // float4 index
    int base = t << 2;
    int j0  = base & 511;
    int i   = (base >> 9) & 511;
    int img = base >> 18;
    int b   = img / 3;
    int2 s  = g_best[b];
    int si  = i - s.x;
    float4 v = make_float4(0.f, 0.f, 0.f, 0.f);
    if ((unsigned)si < (unsigned)HH) {
        int sj  = j0 - s.y;
        int sa  = sj & ~3;
        int off = sj & 3;                        // == (-sy)&3 : warp-uniform
        const float* row = x + ((size_t)img << 18) + (si << 9);
        float4 qa = ((unsigned)sa < (unsigned)WW)
                        ? __ldg((const float4*)(row + sa)) : v;
        float4 qb = ((unsigned)(sa + 4) < (unsigned)WW)
                        ? __ldg((const float4*)(row + sa + 4)) : v;
        switch (off) {
            case 0:  v = qa; break;
            case 1:  v = make_float4(qa.y, qa.z, qa.w, qb.x); break;
            case 2:  v = make_float4(qa.z, qa.w, qb.x, qb.y); break;
            default: v = make_float4(qa.w, qb.x, qb.y, qb.z); break;
        }
    }
    ((float4*)out)[t] = v;
}

// ---------------------------------------------------------------------------
extern "C" void kernel_launch(void* const* d_in, const int* in_sizes, int n_in,
                              void* d_out, int out_size) {
    const float* x_ref = (const float*)d_in[0];
    const float* x     = (const float*)d_in[1];
    float* out = (float*)d_out;

    corr_kernel<<<NBLK, 256>>>(x, x_ref);
    reduce_argmax_kernel<<<1, 384>>>(out, out_size);
    apply_kernel<<<OUT_IMG / 4 / 256, 256>>>(x, out);
}